// round 1
// baseline (speedup 1.0000x reference)
#include <cuda_runtime.h>

#define Hh 56
#define Ww 56
#define WSZ 7
#define SSZ 3
#define NHEAD 8
#define EMB 256
#define HDIM 32
#define NWIN 64
#define WD 49
#define BATCH 32

// Scratch: attention output already in final token order (post reverse-shift),
// laid out (b, r*56+c, e) row-major so proj is a dense GEMM.
__device__ float g_scratch[(size_t)BATCH * Hh * Ww * EMB];

// ---------------------------------------------------------------------------
// Kernel 1: one block per (b, window, head).
// shift-gather -> qkv -> scores(+bias+mask) -> softmax -> AV -> scatter.
// ---------------------------------------------------------------------------
__global__ __launch_bounds__(128) void swin_attn_kernel(
    const float* __restrict__ x,
    const float* __restrict__ qkv_w,
    const float* __restrict__ qkv_b,
    const float* __restrict__ rpb)
{
    __shared__ float s_x[56 * 33];     // window slice [t][d], rows 49..55 zeroed
    __shared__ float s_w[32 * 96];     // qkv weight
    __shared__ float s_b[96];          // qkv bias
    __shared__ float s_qkv[49 * 99];   // q(scaled)|k|v per token, stride 99
    __shared__ float s_rpb[169];       // rel-pos bias column for this head
    __shared__ int   s_ki[49], s_kj[49], s_reg[49];
    __shared__ float s_p[4][52];       // per-warp softmax row

    const int tid = threadIdx.x;
    const int blk = blockIdx.x;
    const int h  = blk & (NHEAD - 1);
    const int w  = (blk >> 3) & (NWIN - 1);
    const int b  = blk >> 9;           // blk / (NHEAD*NWIN)
    const int wi = w >> 3, wj = w & 7;

    // ---- loads ----
    const float* xb = x + (size_t)b * (Hh * Ww * EMB);
    for (int idx = tid; idx < WD * HDIM; idx += 128) {
        int t = idx >> 5, d = idx & 31;
        int ti = t / 7, tj = t % 7;
        int rr = wi * 7 + ti + SSZ; if (rr >= Hh) rr -= Hh;   // cyclic shift gather
        int cc = wj * 7 + tj + SSZ; if (cc >= Ww) cc -= Ww;
        s_x[t * 33 + d] = xb[(size_t)(rr * Ww + cc) * EMB + h * HDIM + d];
    }
    for (int idx = tid; idx < 7 * 33; idx += 128) s_x[49 * 33 + idx] = 0.0f;
    for (int idx = tid; idx < 32 * 96; idx += 128) s_w[idx] = qkv_w[idx];
    if (tid < 96) s_b[tid] = qkv_b[tid];
    for (int idx = tid; idx < 169; idx += 128) s_rpb[idx] = rpb[idx * NHEAD + h];
    if (tid < WD) {
        int ti = tid / 7, tj = tid % 7;
        s_ki[tid] = ti; s_kj[tid] = tj;
        int r = wi * 7 + ti, c = wj * 7 + tj;     // UNshifted grid (mask definition)
        int hi = (r < Hh - WSZ) ? 0 : ((r < Hh - SSZ) ? 1 : 2);
        int ci = (c < Ww - WSZ) ? 0 : ((c < Ww - SSZ) ? 1 : 2);
        s_reg[tid] = hi * 3 + ci;
    }
    __syncthreads();

    // ---- qkv: thread (ty,tx) computes 7 t-rows x 6 j-cols ----
    {
        const int ty = tid >> 4, tx = tid & 15;
        float acc[7][6];
        #pragma unroll
        for (int i = 0; i < 7; i++)
            #pragma unroll
            for (int j = 0; j < 6; j++) acc[i][j] = 0.0f;

        #pragma unroll
        for (int d = 0; d < 32; d++) {
            float a[7], wv[6];
            #pragma unroll
            for (int i = 0; i < 7; i++) a[i] = s_x[(ty + 8 * i) * 33 + d];
            #pragma unroll
            for (int j = 0; j < 6; j++) wv[j] = s_w[d * 96 + tx + 16 * j];
            #pragma unroll
            for (int i = 0; i < 7; i++)
                #pragma unroll
                for (int j = 0; j < 6; j++) acc[i][j] += a[i] * wv[j];
        }
        const float scale = 0.17677669529663687f;  // 1/sqrt(32)
        #pragma unroll
        for (int i = 0; i < 7; i++) {
            int t = ty + 8 * i;
            if (t < WD) {
                #pragma unroll
                for (int j = 0; j < 6; j++) {
                    int jj = tx + 16 * j;
                    float v = acc[i][j] + s_b[jj];
                    if (jj < 32) v *= scale;      // fold 1/sqrt(HD) into q
                    s_qkv[t * 99 + jj] = v;
                }
            }
        }
    }
    __syncthreads();

    // ---- attention: warp ww handles queries t = ww, ww+4, ... ----
    const int ww = tid >> 5, lane = tid & 31;
    float* outb = g_scratch + (size_t)b * (Hh * Ww) * EMB + h * HDIM;

    for (int t = ww; t < WD; t += 4) {
        const int ti = s_ki[t], tj = s_kj[t];
        const int key2 = lane + 32;
        const bool v2 = (key2 < WD);
        const int k2c = v2 ? key2 : 0;

        float s1 = 0.0f, s2 = 0.0f;
        #pragma unroll
        for (int d = 0; d < 32; d++) {
            float qd = s_qkv[t * 99 + d];                 // broadcast
            s1 += qd * s_qkv[lane * 99 + 32 + d];         // conflict-free (stride 3 mod 32)
            s2 += qd * s_qkv[k2c  * 99 + 32 + d];
        }
        // rel-pos bias + shift mask
        {
            int rpi = (ti - s_ki[lane] + 6) * 13 + (tj - s_kj[lane] + 6);
            s1 += s_rpb[rpi];
            if (s_reg[t] != s_reg[lane]) s1 -= 100.0f;
        }
        if (v2) {
            int rpi = (ti - s_ki[k2c] + 6) * 13 + (tj - s_kj[k2c] + 6);
            s2 += s_rpb[rpi];
            if (s_reg[t] != s_reg[k2c]) s2 -= 100.0f;
        } else {
            s2 = -1e30f;
        }
        // softmax over 49 keys (2 per lane)
        float mx = fmaxf(s1, s2);
        #pragma unroll
        for (int o = 16; o > 0; o >>= 1) mx = fmaxf(mx, __shfl_xor_sync(0xffffffffu, mx, o));
        float p1 = __expf(s1 - mx);
        float p2 = v2 ? __expf(s2 - mx) : 0.0f;
        float sm = p1 + p2;
        #pragma unroll
        for (int o = 16; o > 0; o >>= 1) sm += __shfl_xor_sync(0xffffffffu, sm, o);
        float inv = __frcp_rn(sm);
        s_p[ww][lane] = p1 * inv;
        if (v2) s_p[ww][key2] = p2 * inv;
        __syncwarp();

        // AV: lane = output channel d
        float acc = 0.0f;
        #pragma unroll
        for (int key = 0; key < WD; key++)
            acc += s_p[ww][key] * s_qkv[key * 99 + 64 + lane];

        // scatter to final token position (reverse window + reverse shift)
        int rr = wi * 7 + ti + SSZ; if (rr >= Hh) rr -= Hh;
        int cc = wj * 7 + tj + SSZ; if (cc >= Ww) cc -= Ww;
        outb[(size_t)(rr * Ww + cc) * EMB + lane] = acc;
        __syncwarp();
    }
}

// ---------------------------------------------------------------------------
// Kernel 2: proj GEMM  C[100352,256] = scratch @ proj_w + proj_b
// 128x128 block tile, K-step 8, 8x8 microtile per thread.
// ---------------------------------------------------------------------------
__global__ __launch_bounds__(256) void proj_kernel(
    const float* __restrict__ Bw,
    const float* __restrict__ bias,
    float* __restrict__ C)
{
    __shared__ float As[8][132];
    __shared__ float Bs[8][132];

    const int tid = threadIdx.x;
    const int m0 = blockIdx.x * 128;
    const int n0 = blockIdx.y * 128;
    const int row = (tid >> 4) << 3;
    const int col = (tid & 15) << 3;
    const int ar = tid >> 1;
    const int ac = (tid & 1) << 2;
    const int br = tid >> 5;
    const int bc = (tid & 31) << 2;

    const float* Ap = g_scratch + (size_t)(m0 + ar) * 256 + ac;
    const float* Bp = Bw + (size_t)br * 256 + n0 + bc;

    float acc[8][8];
    #pragma unroll
    for (int i = 0; i < 8; i++)
        #pragma unroll
        for (int j = 0; j < 8; j++) acc[i][j] = 0.0f;

    for (int k0 = 0; k0 < 256; k0 += 8) {
        float4 av = *(const float4*)(Ap + k0);
        float4 bv = *(const float4*)(Bp + (size_t)k0 * 256);
        As[ac + 0][ar] = av.x; As[ac + 1][ar] = av.y;
        As[ac + 2][ar] = av.z; As[ac + 3][ar] = av.w;
        *(float4*)&Bs[br][bc] = bv;
        __syncthreads();

        #pragma unroll
        for (int kk = 0; kk < 8; kk++) {
            float a[8], bb[8];
            *(float4*)&a[0]  = *(const float4*)&As[kk][row];
            *(float4*)&a[4]  = *(const float4*)&As[kk][row + 4];
            *(float4*)&bb[0] = *(const float4*)&Bs[kk][col];
            *(float4*)&bb[4] = *(const float4*)&Bs[kk][col + 4];
            #pragma unroll
            for (int i = 0; i < 8; i++)
                #pragma unroll
                for (int j = 0; j < 8; j++) acc[i][j] += a[i] * bb[j];
        }
        __syncthreads();
    }

    float bs[8];
    #pragma unroll
    for (int j = 0; j < 8; j++) bs[j] = bias[n0 + col + j];

    #pragma unroll
    for (int i = 0; i < 8; i++) {
        float4 o0, o1;
        o0.x = acc[i][0] + bs[0]; o0.y = acc[i][1] + bs[1];
        o0.z = acc[i][2] + bs[2]; o0.w = acc[i][3] + bs[3];
        o1.x = acc[i][4] + bs[4]; o1.y = acc[i][5] + bs[5];
        o1.z = acc[i][6] + bs[6]; o1.w = acc[i][7] + bs[7];
        float* cp = C + (size_t)(m0 + row + i) * 256 + n0 + col;
        *(float4*)(cp)     = o0;
        *(float4*)(cp + 4) = o1;
    }
}

// ---------------------------------------------------------------------------
extern "C" void kernel_launch(void* const* d_in, const int* in_sizes, int n_in,
                              void* d_out, int out_size)
{
    const float* x      = (const float*)d_in[0];
    const float* qkv_w  = (const float*)d_in[1];
    const float* qkv_b  = (const float*)d_in[2];
    const float* proj_w = (const float*)d_in[3];
    const float* proj_b = (const float*)d_in[4];
    const float* rpb    = (const float*)d_in[5];

    swin_attn_kernel<<<BATCH * NWIN * NHEAD, 128>>>(x, qkv_w, qkv_b, rpb);
    proj_kernel<<<dim3(784, 2), 256>>>(proj_w, proj_b, (float*)d_out);
}

// round 5
// speedup vs baseline: 1.1650x; 1.1650x over previous
#include <cuda_runtime.h>
#include <cuda_bf16.h>
#include <cstdint>

#define Hh 56
#define Ww 56
#define WSZ 7
#define SSZ 3
#define NHEAD 8
#define EMB 256
#define HDIM 32
#define NWIN 64
#define WD 49
#define BATCH 32

// Scratch: attention output already in final token order (post reverse-shift),
// laid out (b, r*56+c, e) row-major so proj is a dense GEMM.
__device__ float g_scratch[(size_t)BATCH * Hh * Ww * EMB];

// ---------------------------------------------------------------------------
// Kernel 1 (unchanged from R1): one block per (b, window, head).
// ---------------------------------------------------------------------------
__global__ __launch_bounds__(128) void swin_attn_kernel(
    const float* __restrict__ x,
    const float* __restrict__ qkv_w,
    const float* __restrict__ qkv_b,
    const float* __restrict__ rpb)
{
    __shared__ float s_x[56 * 33];
    __shared__ float s_w[32 * 96];
    __shared__ float s_b[96];
    __shared__ float s_qkv[49 * 99];
    __shared__ float s_rpb[169];
    __shared__ int   s_ki[49], s_kj[49], s_reg[49];
    __shared__ float s_p[4][52];

    const int tid = threadIdx.x;
    const int blk = blockIdx.x;
    const int h  = blk & (NHEAD - 1);
    const int w  = (blk >> 3) & (NWIN - 1);
    const int b  = blk >> 9;
    const int wi = w >> 3, wj = w & 7;

    const float* xb = x + (size_t)b * (Hh * Ww * EMB);
    for (int idx = tid; idx < WD * HDIM; idx += 128) {
        int t = idx >> 5, d = idx & 31;
        int ti = t / 7, tj = t % 7;
        int rr = wi * 7 + ti + SSZ; if (rr >= Hh) rr -= Hh;
        int cc = wj * 7 + tj + SSZ; if (cc >= Ww) cc -= Ww;
        s_x[t * 33 + d] = xb[(size_t)(rr * Ww + cc) * EMB + h * HDIM + d];
    }
    for (int idx = tid; idx < 7 * 33; idx += 128) s_x[49 * 33 + idx] = 0.0f;
    for (int idx = tid; idx < 32 * 96; idx += 128) s_w[idx] = qkv_w[idx];
    if (tid < 96) s_b[tid] = qkv_b[tid];
    for (int idx = tid; idx < 169; idx += 128) s_rpb[idx] = rpb[idx * NHEAD + h];
    if (tid < WD) {
        int ti = tid / 7, tj = tid % 7;
        s_ki[tid] = ti; s_kj[tid] = tj;
        int r = wi * 7 + ti, c = wj * 7 + tj;
        int hi = (r < Hh - WSZ) ? 0 : ((r < Hh - SSZ) ? 1 : 2);
        int ci = (c < Ww - WSZ) ? 0 : ((c < Ww - SSZ) ? 1 : 2);
        s_reg[tid] = hi * 3 + ci;
    }
    __syncthreads();

    {
        const int ty = tid >> 4, tx = tid & 15;
        float acc[7][6];
        #pragma unroll
        for (int i = 0; i < 7; i++)
            #pragma unroll
            for (int j = 0; j < 6; j++) acc[i][j] = 0.0f;

        #pragma unroll
        for (int d = 0; d < 32; d++) {
            float a[7], wv[6];
            #pragma unroll
            for (int i = 0; i < 7; i++) a[i] = s_x[(ty + 8 * i) * 33 + d];
            #pragma unroll
            for (int j = 0; j < 6; j++) wv[j] = s_w[d * 96 + tx + 16 * j];
            #pragma unroll
            for (int i = 0; i < 7; i++)
                #pragma unroll
                for (int j = 0; j < 6; j++) acc[i][j] += a[i] * wv[j];
        }
        const float scale = 0.17677669529663687f;
        #pragma unroll
        for (int i = 0; i < 7; i++) {
            int t = ty + 8 * i;
            if (t < WD) {
                #pragma unroll
                for (int j = 0; j < 6; j++) {
                    int jj = tx + 16 * j;
                    float v = acc[i][j] + s_b[jj];
                    if (jj < 32) v *= scale;
                    s_qkv[t * 99 + jj] = v;
                }
            }
        }
    }
    __syncthreads();

    const int ww = tid >> 5, lane = tid & 31;
    float* outb = g_scratch + (size_t)b * (Hh * Ww) * EMB + h * HDIM;

    for (int t = ww; t < WD; t += 4) {
        const int ti = s_ki[t], tj = s_kj[t];
        const int key2 = lane + 32;
        const bool v2 = (key2 < WD);
        const int k2c = v2 ? key2 : 0;

        float s1 = 0.0f, s2 = 0.0f;
        #pragma unroll
        for (int d = 0; d < 32; d++) {
            float qd = s_qkv[t * 99 + d];
            s1 += qd * s_qkv[lane * 99 + 32 + d];
            s2 += qd * s_qkv[k2c  * 99 + 32 + d];
        }
        {
            int rpi = (ti - s_ki[lane] + 6) * 13 + (tj - s_kj[lane] + 6);
            s1 += s_rpb[rpi];
            if (s_reg[t] != s_reg[lane]) s1 -= 100.0f;
        }
        if (v2) {
            int rpi = (ti - s_ki[k2c] + 6) * 13 + (tj - s_kj[k2c] + 6);
            s2 += s_rpb[rpi];
            if (s_reg[t] != s_reg[k2c]) s2 -= 100.0f;
        } else {
            s2 = -1e30f;
        }
        float mx = fmaxf(s1, s2);
        #pragma unroll
        for (int o = 16; o > 0; o >>= 1) mx = fmaxf(mx, __shfl_xor_sync(0xffffffffu, mx, o));
        float p1 = __expf(s1 - mx);
        float p2 = v2 ? __expf(s2 - mx) : 0.0f;
        float sm = p1 + p2;
        #pragma unroll
        for (int o = 16; o > 0; o >>= 1) sm += __shfl_xor_sync(0xffffffffu, sm, o);
        float inv = __frcp_rn(sm);
        s_p[ww][lane] = p1 * inv;
        if (v2) s_p[ww][key2] = p2 * inv;
        __syncwarp();

        float acc = 0.0f;
        #pragma unroll
        for (int key = 0; key < WD; key++)
            acc += s_p[ww][key] * s_qkv[key * 99 + 64 + lane];

        int rr = wi * 7 + ti + SSZ; if (rr >= Hh) rr -= Hh;
        int cc = wj * 7 + tj + SSZ; if (cc >= Ww) cc -= Ww;
        outb[(size_t)(rr * Ww + cc) * EMB + lane] = acc;
        __syncwarp();
    }
}

// ---------------------------------------------------------------------------
// Kernel 2: proj GEMM via mma.sync bf16 (split hi/lo, 3 products = fp32-grade).
// C[100352,256] = g_scratch @ proj_w + proj_b
// Block: 128x128 tile, 8 warps of 32x64, K chunked by 32.
// ---------------------------------------------------------------------------
#define PLD 40  // padded smem row length in bf16 elems (80B -> conflict-free frags)

__device__ __forceinline__ uint32_t sm32(const void* p) {
    uint32_t a;
    asm("{ .reg .u64 t; cvta.to.shared.u64 t, %1; cvt.u32.u64 %0, t; }" : "=r"(a) : "l"(p));
    return a;
}
__device__ __forceinline__ uint32_t pack_bf2(float x, float y) {
    __nv_bfloat162 v = __floats2bfloat162_rn(x, y);
    return *(uint32_t*)&v;
}
__device__ __forceinline__ void mma16816(float* d, const uint32_t* a, const uint32_t* b) {
    asm volatile(
        "mma.sync.aligned.m16n8k16.row.col.f32.bf16.bf16.f32 "
        "{%0,%1,%2,%3}, {%4,%5,%6,%7}, {%8,%9}, {%0,%1,%2,%3};"
        : "+f"(d[0]), "+f"(d[1]), "+f"(d[2]), "+f"(d[3])
        : "r"(a[0]), "r"(a[1]), "r"(a[2]), "r"(a[3]), "r"(b[0]), "r"(b[1]));
}

__global__ __launch_bounds__(256) void proj_mma_kernel(
    const float* __restrict__ Wt,
    const float* __restrict__ bias,
    float* __restrict__ C)
{
    __shared__ __align__(16) uint16_t sA[2][128 * PLD];  // [hi/lo][row][k]
    __shared__ __align__(16) uint16_t sB[2][128 * PLD];  // [hi/lo][n][k]

    const int tid  = threadIdx.x;
    const int wid  = tid >> 5, lane = tid & 31;
    const int g    = lane >> 2, t4 = lane & 3;       // mma group / thread-in-group
    const int wm   = wid & 3, wn = wid >> 2;         // warp tile: rows wm*32, cols wn*64
    const int m0   = blockIdx.x * 128, n0 = blockIdx.y * 128;

    float acc[2][8][4];
    #pragma unroll
    for (int i = 0; i < 2; i++)
        #pragma unroll
        for (int j = 0; j < 8; j++)
            #pragma unroll
            for (int r = 0; r < 4; r++) acc[i][j][r] = 0.0f;

    for (int k0 = 0; k0 < 256; k0 += 32) {
        // ---- stage A chunk: 128 rows x 32 k, fp32 -> hi/lo bf16 ----
        #pragma unroll
        for (int i = 0; i < 4; i++) {
            int idx = tid + 256 * i;          // 1024 float4 slots
            int r = idx >> 3, c4 = (idx & 7) << 2;
            float4 v = *(const float4*)(g_scratch + (size_t)(m0 + r) * 256 + k0 + c4);
            uint32_t h0 = pack_bf2(v.x, v.y), h1 = pack_bf2(v.z, v.w);
            float rx = v.x - __bfloat162float(__ushort_as_bfloat16((uint16_t)h0));
            float ry = v.y - __bfloat162float(__ushort_as_bfloat16((uint16_t)(h0 >> 16)));
            float rz = v.z - __bfloat162float(__ushort_as_bfloat16((uint16_t)h1));
            float rw = v.w - __bfloat162float(__ushort_as_bfloat16((uint16_t)(h1 >> 16)));
            *(uint2*)&sA[0][r * PLD + c4] = make_uint2(h0, h1);
            *(uint2*)&sA[1][r * PLD + c4] = make_uint2(pack_bf2(rx, ry), pack_bf2(rz, rw));
        }
        // ---- stage B chunk: sB[n][k] = W[k0+k][n0+n], transposed on the fly ----
        #pragma unroll
        for (int i = 0; i < 4; i++) {
            int idx = tid + 256 * i;          // 1024 = 128 n x 8 kg
            int n = idx & 127, kg = idx >> 7; // kg in 0..7, 4 k each
            float w0 = Wt[(size_t)(k0 + kg * 4 + 0) * 256 + n0 + n];
            float w1 = Wt[(size_t)(k0 + kg * 4 + 1) * 256 + n0 + n];
            float w2 = Wt[(size_t)(k0 + kg * 4 + 2) * 256 + n0 + n];
            float w3 = Wt[(size_t)(k0 + kg * 4 + 3) * 256 + n0 + n];
            uint32_t h0 = pack_bf2(w0, w1), h1 = pack_bf2(w2, w3);
            float r0 = w0 - __bfloat162float(__ushort_as_bfloat16((uint16_t)h0));
            float r1 = w1 - __bfloat162float(__ushort_as_bfloat16((uint16_t)(h0 >> 16)));
            float r2 = w2 - __bfloat162float(__ushort_as_bfloat16((uint16_t)h1));
            float r3 = w3 - __bfloat162float(__ushort_as_bfloat16((uint16_t)(h1 >> 16)));
            *(uint2*)&sB[0][n * PLD + kg * 4] = make_uint2(h0, h1);
            *(uint2*)&sB[1][n * PLD + kg * 4] = make_uint2(pack_bf2(r0, r1), pack_bf2(r2, r3));
        }
        __syncthreads();

        // ---- two k16 sub-steps ----
        #pragma unroll
        for (int ks = 0; ks < 32; ks += 16) {
            uint32_t ah[2][4], al[2][4], bh[8][2], bl[8][2];
            #pragma unroll
            for (int tm = 0; tm < 2; tm++) {
                int row = wm * 32 + tm * 16 + g;
                int kc  = ks + t4 * 2;
                ah[tm][0] = *(const uint32_t*)&sA[0][row * PLD + kc];
                ah[tm][1] = *(const uint32_t*)&sA[0][(row + 8) * PLD + kc];
                ah[tm][2] = *(const uint32_t*)&sA[0][row * PLD + kc + 8];
                ah[tm][3] = *(const uint32_t*)&sA[0][(row + 8) * PLD + kc + 8];
                al[tm][0] = *(const uint32_t*)&sA[1][row * PLD + kc];
                al[tm][1] = *(const uint32_t*)&sA[1][(row + 8) * PLD + kc];
                al[tm][2] = *(const uint32_t*)&sA[1][row * PLD + kc + 8];
                al[tm][3] = *(const uint32_t*)&sA[1][(row + 8) * PLD + kc + 8];
            }
            #pragma unroll
            for (int tn = 0; tn < 8; tn++) {
                int n  = wn * 64 + tn * 8 + g;
                int kc = ks + t4 * 2;
                bh[tn][0] = *(const uint32_t*)&sB[0][n * PLD + kc];
                bh[tn][1] = *(const uint32_t*)&sB[0][n * PLD + kc + 8];
                bl[tn][0] = *(const uint32_t*)&sB[1][n * PLD + kc];
                bl[tn][1] = *(const uint32_t*)&sB[1][n * PLD + kc + 8];
            }
            #pragma unroll
            for (int tm = 0; tm < 2; tm++)
                #pragma unroll
                for (int tn = 0; tn < 8; tn++) {
                    mma16816(acc[tm][tn], ah[tm], bh[tn]);
                    mma16816(acc[tm][tn], ah[tm], bl[tn]);
                    mma16816(acc[tm][tn], al[tm], bh[tn]);
                }
        }
        __syncthreads();
    }

    // ---- epilogue: direct register -> gmem with bias ----
    #pragma unroll
    for (int tm = 0; tm < 2; tm++) {
        int row = m0 + wm * 32 + tm * 16 + g;
        #pragma unroll
        for (int tn = 0; tn < 8; tn++) {
            int col = n0 + wn * 64 + tn * 8 + t4 * 2;
            float b0 = bias[col], b1 = bias[col + 1];
            *(float2*)(C + (size_t)row * 256 + col) =
                make_float2(acc[tm][tn][0] + b0, acc[tm][tn][1] + b1);
            *(float2*)(C + (size_t)(row + 8) * 256 + col) =
                make_float2(acc[tm][tn][2] + b0, acc[tm][tn][3] + b1);
        }
    }
}

// ---------------------------------------------------------------------------
extern "C" void kernel_launch(void* const* d_in, const int* in_sizes, int n_in,
                              void* d_out, int out_size)
{
    const float* x      = (const float*)d_in[0];
    const float* qkv_w  = (const float*)d_in[1];
    const float* qkv_b  = (const float*)d_in[2];
    const float* proj_w = (const float*)d_in[3];
    const float* proj_b = (const float*)d_in[4];
    const float* rpb    = (const float*)d_in[5];

    swin_attn_kernel<<<BATCH * NWIN * NHEAD, 128>>>(x, qkv_w, qkv_b, rpb);
    proj_mma_kernel<<<dim3(784, 2), 256>>>(proj_w, proj_b, (float*)d_out);
}

// round 7
// speedup vs baseline: 2.1848x; 1.8754x over previous
#include <cuda_runtime.h>
#include <cuda_bf16.h>
#include <cstdint>

#define Hh 56
#define Ww 56
#define WSZ 7
#define SSZ 3
#define NHEAD 8
#define EMB 256
#define HDIM 32
#define NWIN 64
#define WD 49
#define BATCH 32
#define FULLMASK 0xffffffffu

__device__ float g_scratch[(size_t)BATCH * Hh * Ww * EMB];

// ---------------------------------------------------------------------------
// helpers
// ---------------------------------------------------------------------------
__device__ __forceinline__ uint32_t pack_bf2(float x, float y) {
    __nv_bfloat162 v = __floats2bfloat162_rn(x, y);
    return *(uint32_t*)&v;
}
__device__ __forceinline__ float bflo(uint32_t u) {
    return __bfloat162float(__ushort_as_bfloat16((uint16_t)u));
}
__device__ __forceinline__ float bfhi(uint32_t u) {
    return __bfloat162float(__ushort_as_bfloat16((uint16_t)(u >> 16)));
}
__device__ __forceinline__ void mma16816(float* d, const uint32_t* a, const uint32_t* b) {
    asm volatile(
        "mma.sync.aligned.m16n8k16.row.col.f32.bf16.bf16.f32 "
        "{%0,%1,%2,%3}, {%4,%5,%6,%7}, {%8,%9}, {%0,%1,%2,%3};"
        : "+f"(d[0]), "+f"(d[1]), "+f"(d[2]), "+f"(d[3])
        : "r"(a[0]), "r"(a[1]), "r"(a[2]), "r"(a[3]), "r"(b[0]), "r"(b[1]));
}
__device__ __forceinline__ void ldsm4(uint32_t a, uint32_t* r) {
    asm volatile("ldmatrix.sync.aligned.m8n8.x4.shared.b16 {%0,%1,%2,%3}, [%4];"
                 : "=r"(r[0]), "=r"(r[1]), "=r"(r[2]), "=r"(r[3]) : "r"(a));
}
__device__ __forceinline__ void ldsm2(uint32_t a, uint32_t* r) {
    asm volatile("ldmatrix.sync.aligned.m8n8.x2.shared.b16 {%0,%1}, [%2];"
                 : "=r"(r[0]), "=r"(r[1]) : "r"(a));
}
__device__ __forceinline__ uint32_t sm32(const void* p) {
    uint32_t a;
    asm("{ .reg .u64 t; cvta.to.shared.u64 t, %1; cvt.u32.u64 %0, t; }" : "=r"(a) : "l"(p));
    return a;
}

// ---------------------------------------------------------------------------
// smem layout (bytes)
// ---------------------------------------------------------------------------
#define OFF_XHI   0
#define OFF_XLO   33792           // 64*264*2
#define OFF_WHI   67584
#define OFF_WLO   75264           // 96*40*2
#define HEADS_OFF 82944
#define HEAD_SZ   29696
#define Q_HI      0
#define Q_LO      5120            // 64*40*2
#define K_HI      10240
#define K_LO      15360
#define V_HI      20480           // 32*72*2
#define V_LO      25088
#define OFF_RPB   201728          // fp32 8*169
#define OFF_TI    207136
#define OFF_TJ    207392
#define OFF_REG   207648
#define OFF_DST   207904
#define OFF_QB    208160          // fp32 96
#define SMEM_TOT  208544

// ---------------------------------------------------------------------------
// Kernel 1: one block per (b, window). All heads via mma.sync bf16 split hi/lo.
// ---------------------------------------------------------------------------
__global__ __launch_bounds__(256, 1) void swin_attn_tc(
    const float* __restrict__ x,
    const float* __restrict__ qkv_w,
    const float* __restrict__ qkv_b,
    const float* __restrict__ rpb)
{
    extern __shared__ __align__(16) char dsm[];
    const uint32_t sb = sm32(dsm);

    float* s_rpb = (float*)(dsm + OFF_RPB);
    int*   s_ti  = (int*)(dsm + OFF_TI);
    int*   s_tj  = (int*)(dsm + OFF_TJ);
    int*   s_reg = (int*)(dsm + OFF_REG);
    int*   s_dst = (int*)(dsm + OFF_DST);
    float* s_qb  = (float*)(dsm + OFF_QB);

    const int tid = threadIdx.x;
    const int wid = tid >> 5, lane = tid & 31;
    const int g = lane >> 2, t4 = lane & 3;
    const int w = blockIdx.x & (NWIN - 1);
    const int b = blockIdx.x >> 6;
    const int wi = w >> 3, wj = w & 7;
    const float SCALE = 0.17677669529663687f;

    // ---- stage 0: LUTs ----
    if (tid < 64) {
        int t = tid;
        int ti = 0, tj = 0, rg = 9, dst = 0;
        if (t < WD) {
            ti = t / 7; tj = t % 7;
            int r = wi * 7 + ti, c = wj * 7 + tj;
            int hi2 = (r < Hh - WSZ) ? 0 : ((r < Hh - SSZ) ? 1 : 2);
            int ci2 = (c < Ww - WSZ) ? 0 : ((c < Ww - SSZ) ? 1 : 2);
            rg = hi2 * 3 + ci2;
            int rr = wi * 7 + ti + SSZ; if (rr >= Hh) rr -= Hh;
            int cc = wj * 7 + tj + SSZ; if (cc >= Ww) cc -= Ww;
            dst = (rr * Ww + cc) * EMB;
        }
        s_ti[t] = ti; s_tj[t] = tj; s_reg[t] = rg; s_dst[t] = dst;
    }
    if (tid < 96) {
        float v = qkv_b[tid];
        if (tid < 32) v *= SCALE;
        s_qb[tid] = v;
    }
    for (int idx = tid; idx < 8 * 169; idx += 256) {
        int h = idx / 169, i = idx - h * 169;
        s_rpb[h * 169 + i] = rpb[i * NHEAD + h];
    }
    // wT[j][d] hi/lo (fold q-scale into j<32)
    for (int idx = tid; idx < 96 * 32; idx += 256) {
        int j = idx >> 5, d = idx & 31;
        float v = qkv_w[d * 96 + j];
        if (j < 32) v *= SCALE;
        __nv_bfloat16 hb = __float2bfloat16(v);
        *(uint16_t*)(dsm + OFF_WHI + (j * 40 + d) * 2) = __bfloat16_as_ushort(hb);
        __nv_bfloat16 lb = __float2bfloat16(v - __bfloat162float(hb));
        *(uint16_t*)(dsm + OFF_WLO + (j * 40 + d) * 2) = __bfloat16_as_ushort(lb);
    }
    __syncthreads();   // s_dst needed for X gather

    // ---- X window gather + bf16 hi/lo split ----
    const float* xb = x + (size_t)b * (Hh * Ww * EMB);
    for (int idx = tid; idx < WD * 64; idx += 256) {
        int r = idx >> 6, c4 = (idx & 63) << 2;
        float4 v = *(const float4*)(xb + s_dst[r] + c4);
        uint32_t h0 = pack_bf2(v.x, v.y), h1 = pack_bf2(v.z, v.w);
        float lx = v.x - bflo(h0), ly = v.y - bfhi(h0);
        float lz = v.z - bflo(h1), lw = v.w - bfhi(h1);
        *(uint2*)(dsm + OFF_XHI + (r * 264 + c4) * 2) = make_uint2(h0, h1);
        *(uint2*)(dsm + OFF_XLO + (r * 264 + c4) * 2) = make_uint2(pack_bf2(lx, ly), pack_bf2(lz, lw));
    }
    for (int idx = tid; idx < 15 * 132; idx += 256) {   // zero pad rows 49..63
        *(uint32_t*)(dsm + OFF_XHI + WD * 528 + idx * 4) = 0u;
        *(uint32_t*)(dsm + OFF_XLO + WD * 528 + idx * 4) = 0u;
    }
    __syncthreads();

    const int slot = wid >> 1;                 // head slot 0..3
    const int sub  = wid & 1;                  // query-row half
    const int rbase = sub * 32;
    const uint32_t HB = sb + HEADS_OFF + slot * HEAD_SZ;

    for (int pass = 0; pass < 2; pass++) {
        const int h = pass * 4 + slot;

        // ================= phase A: qkv for head h, rows [rbase, rbase+32) =====
        {
            uint32_t ah[2][2][4], al[2][2][4];
            #pragma unroll
            for (int mt = 0; mt < 2; mt++)
                #pragma unroll
                for (int kt = 0; kt < 2; kt++) {
                    int row = rbase + mt * 16 + (lane & 15);
                    int col = h * 32 + kt * 16 + ((lane >> 4) & 1) * 8;
                    ldsm4(sb + OFF_XHI + (row * 264 + col) * 2, ah[mt][kt]);
                    ldsm4(sb + OFF_XLO + (row * 264 + col) * 2, al[mt][kt]);
                }

            #pragma unroll 1
            for (int nt = 0; nt < 12; nt++) {
                uint32_t bh[2][2], bl[2][2];
                #pragma unroll
                for (int kt = 0; kt < 2; kt++) {
                    int row = nt * 8 + (lane & 7);
                    int col = kt * 16 + ((lane >> 3) & 1) * 8;
                    ldsm2(sb + OFF_WHI + (row * 40 + col) * 2, bh[kt]);
                    ldsm2(sb + OFF_WLO + (row * 40 + col) * 2, bl[kt]);
                }
                int j0 = nt * 8 + 2 * t4;
                float b0 = s_qb[j0], b1 = s_qb[j0 + 1];
                #pragma unroll
                for (int mt = 0; mt < 2; mt++) {
                    float c[4] = {0.f, 0.f, 0.f, 0.f};
                    #pragma unroll
                    for (int kt = 0; kt < 2; kt++) {
                        mma16816(c, ah[mt][kt], bh[kt]);
                        mma16816(c, ah[mt][kt], bl[kt]);
                        mma16816(c, al[mt][kt], bh[kt]);
                    }
                    int rlo = rbase + mt * 16 + g, rhi = rlo + 8;
                    float v0 = c[0] + b0, v1 = c[1] + b1;
                    float v2 = c[2] + b0, v3 = c[3] + b1;
                    if (nt < 8) {
                        uint32_t baseH = (nt < 4) ? HB + Q_HI : HB + K_HI;
                        uint32_t baseL = (nt < 4) ? HB + Q_LO : HB + K_LO;
                        int jc = (nt & 3) * 8 + 2 * t4;
                        uint32_t p0 = pack_bf2(v0, v1);
                        uint32_t p1 = pack_bf2(v2, v3);
                        *(uint32_t*)(dsm + (baseH - sb) + (rlo * 40 + jc) * 2) = p0;
                        *(uint32_t*)(dsm + (baseH - sb) + (rhi * 40 + jc) * 2) = p1;
                        *(uint32_t*)(dsm + (baseL - sb) + (rlo * 40 + jc) * 2) =
                            pack_bf2(v0 - bflo(p0), v1 - bfhi(p0));
                        *(uint32_t*)(dsm + (baseL - sb) + (rhi * 40 + jc) * 2) =
                            pack_bf2(v2 - bflo(p1), v3 - bfhi(p1));
                    } else {
                        int d0 = (nt - 8) * 8 + 2 * t4;
                        float vv[4] = {v0, v1, v2, v3};
                        #pragma unroll
                        for (int e = 0; e < 4; e++) {
                            int dd = d0 + (e & 1);
                            int tt = (e < 2) ? rlo : rhi;
                            __nv_bfloat16 hb = __float2bfloat16(vv[e]);
                            *(uint16_t*)(dsm + (HB + V_HI - sb) + (dd * 72 + tt) * 2) =
                                __bfloat16_as_ushort(hb);
                            __nv_bfloat16 lb = __float2bfloat16(vv[e] - __bfloat162float(hb));
                            *(uint16_t*)(dsm + (HB + V_LO - sb) + (dd * 72 + tt) * 2) =
                                __bfloat16_as_ushort(lb);
                        }
                    }
                }
            }
        }
        __syncthreads();

        // ================= phase B: scores + softmax + AV =====================
        {
            uint32_t qh[2][2][4], ql[2][2][4];
            #pragma unroll
            for (int mt = 0; mt < 2; mt++)
                #pragma unroll
                for (int kt = 0; kt < 2; kt++) {
                    int row = rbase + mt * 16 + (lane & 15);
                    int col = kt * 16 + ((lane >> 4) & 1) * 8;
                    ldsm4(HB + Q_HI + (row * 40 + col) * 2, qh[mt][kt]);
                    ldsm4(HB + Q_LO + (row * 40 + col) * 2, ql[mt][kt]);
                }

            float s[2][8][4];
            #pragma unroll
            for (int mt = 0; mt < 2; mt++)
                #pragma unroll
                for (int nt = 0; nt < 8; nt++)
                    #pragma unroll
                    for (int e = 0; e < 4; e++) s[mt][nt][e] = 0.f;

            #pragma unroll
            for (int nt = 0; nt < 8; nt++) {
                uint32_t kh[2][2], kl[2][2];
                #pragma unroll
                for (int kt = 0; kt < 2; kt++) {
                    int row = nt * 8 + (lane & 7);
                    int col = kt * 16 + ((lane >> 3) & 1) * 8;
                    ldsm2(HB + K_HI + (row * 40 + col) * 2, kh[kt]);
                    ldsm2(HB + K_LO + (row * 40 + col) * 2, kl[kt]);
                }
                #pragma unroll
                for (int mt = 0; mt < 2; mt++)
                    #pragma unroll
                    for (int kt = 0; kt < 2; kt++) {
                        mma16816(s[mt][nt], qh[mt][kt], kh[kt]);
                        mma16816(s[mt][nt], qh[mt][kt], kl[kt]);
                        mma16816(s[mt][nt], ql[mt][kt], kh[kt]);
                    }
            }

            // bias + mask + key padding
            int R[4], qi[4], qj[4], qr[4];
            #pragma unroll
            for (int rr = 0; rr < 4; rr++) {
                R[rr] = rbase + g + rr * 8;
                qi[rr] = s_ti[R[rr]]; qj[rr] = s_tj[R[rr]]; qr[rr] = s_reg[R[rr]];
            }
            #pragma unroll
            for (int nt = 0; nt < 8; nt++)
                #pragma unroll
                for (int e01 = 0; e01 < 2; e01++) {
                    int c = nt * 8 + 2 * t4 + e01;
                    if (c < WD) {
                        int ki = s_ti[c], kj = s_tj[c], kr = s_reg[c];
                        #pragma unroll
                        for (int rr = 0; rr < 4; rr++) {
                            float bsum = s_rpb[h * 169 + (qi[rr] - ki + 6) * 13 + (qj[rr] - kj + 6)];
                            if (qr[rr] != kr) bsum -= 100.0f;
                            s[rr >> 1][nt][(rr & 1) * 2 + e01] += bsum;
                        }
                    } else {
                        #pragma unroll
                        for (int rr = 0; rr < 4; rr++)
                            s[rr >> 1][nt][(rr & 1) * 2 + e01] = -1e30f;
                    }
                }

            // softmax per row (width-4 shfl groups)
            float mx[4] = {-1e30f, -1e30f, -1e30f, -1e30f};
            #pragma unroll
            for (int nt = 0; nt < 8; nt++)
                #pragma unroll
                for (int rr = 0; rr < 4; rr++) {
                    mx[rr] = fmaxf(mx[rr], s[rr >> 1][nt][(rr & 1) * 2]);
                    mx[rr] = fmaxf(mx[rr], s[rr >> 1][nt][(rr & 1) * 2 + 1]);
                }
            #pragma unroll
            for (int rr = 0; rr < 4; rr++) {
                mx[rr] = fmaxf(mx[rr], __shfl_xor_sync(FULLMASK, mx[rr], 1));
                mx[rr] = fmaxf(mx[rr], __shfl_xor_sync(FULLMASK, mx[rr], 2));
            }
            float sm[4] = {0.f, 0.f, 0.f, 0.f};
            #pragma unroll
            for (int nt = 0; nt < 8; nt++)
                #pragma unroll
                for (int rr = 0; rr < 4; rr++)
                    #pragma unroll
                    for (int e01 = 0; e01 < 2; e01++) {
                        float p = __expf(s[rr >> 1][nt][(rr & 1) * 2 + e01] - mx[rr]);
                        s[rr >> 1][nt][(rr & 1) * 2 + e01] = p;
                        sm[rr] += p;
                    }
            #pragma unroll
            for (int rr = 0; rr < 4; rr++) {
                sm[rr] += __shfl_xor_sync(FULLMASK, sm[rr], 1);
                sm[rr] += __shfl_xor_sync(FULLMASK, sm[rr], 2);
                sm[rr] = __frcp_rn(sm[rr]);
            }
            #pragma unroll
            for (int nt = 0; nt < 8; nt++)
                #pragma unroll
                for (int rr = 0; rr < 4; rr++)
                    #pragma unroll
                    for (int e01 = 0; e01 < 2; e01++)
                        s[rr >> 1][nt][(rr & 1) * 2 + e01] *= sm[rr];

            // AV
            float o[2][4][4];
            #pragma unroll
            for (int mt = 0; mt < 2; mt++)
                #pragma unroll
                for (int vn = 0; vn < 4; vn++)
                    #pragma unroll
                    for (int e = 0; e < 4; e++) o[mt][vn][e] = 0.f;

            #pragma unroll
            for (int kt = 0; kt < 4; kt++) {
                uint32_t ph[2][4], pl[2][4];
                #pragma unroll
                for (int mt = 0; mt < 2; mt++) {
                    float p0 = s[mt][2 * kt][0], p1 = s[mt][2 * kt][1];
                    float p2 = s[mt][2 * kt][2], p3 = s[mt][2 * kt][3];
                    float p4 = s[mt][2 * kt + 1][0], p5 = s[mt][2 * kt + 1][1];
                    float p6 = s[mt][2 * kt + 1][2], p7 = s[mt][2 * kt + 1][3];
                    ph[mt][0] = pack_bf2(p0, p1); ph[mt][1] = pack_bf2(p2, p3);
                    ph[mt][2] = pack_bf2(p4, p5); ph[mt][3] = pack_bf2(p6, p7);
                    pl[mt][0] = pack_bf2(p0 - bflo(ph[mt][0]), p1 - bfhi(ph[mt][0]));
                    pl[mt][1] = pack_bf2(p2 - bflo(ph[mt][1]), p3 - bfhi(ph[mt][1]));
                    pl[mt][2] = pack_bf2(p4 - bflo(ph[mt][2]), p5 - bfhi(ph[mt][2]));
                    pl[mt][3] = pack_bf2(p6 - bflo(ph[mt][3]), p7 - bfhi(ph[mt][3]));
                }
                #pragma unroll
                for (int vn = 0; vn < 4; vn++) {
                    uint32_t bh[2], bl[2];
                    int row = vn * 8 + (lane & 7);
                    int col = kt * 16 + ((lane >> 3) & 1) * 8;
                    ldsm2(HB + V_HI + (row * 72 + col) * 2, bh);
                    ldsm2(HB + V_LO + (row * 72 + col) * 2, bl);
                    #pragma unroll
                    for (int mt = 0; mt < 2; mt++) {
                        mma16816(o[mt][vn], ph[mt], bh);
                        mma16816(o[mt][vn], ph[mt], bl);
                        mma16816(o[mt][vn], pl[mt], bh);
                    }
                }
            }

            // scatter output
            float* ob = g_scratch + (size_t)b * (Hh * Ww * EMB) + h * HDIM;
            #pragma unroll
            for (int rr = 0; rr < 4; rr++) {
                if (R[rr] < WD) {
                    float* orow = ob + s_dst[R[rr]];
                    int mt = rr >> 1, e = (rr & 1) * 2;
                    #pragma unroll
                    for (int vn = 0; vn < 4; vn++) {
                        int d = vn * 8 + 2 * t4;
                        *(float2*)(orow + d) = make_float2(o[mt][vn][e], o[mt][vn][e + 1]);
                    }
                }
            }
        }
        __syncthreads();
    }
}

// ---------------------------------------------------------------------------
// Kernel 2 (unchanged from R5): proj GEMM via mma.sync split-bf16.
// ---------------------------------------------------------------------------
#define PLD 40

__global__ __launch_bounds__(256) void proj_mma_kernel(
    const float* __restrict__ Wt,
    const float* __restrict__ bias,
    float* __restrict__ C)
{
    __shared__ __align__(16) uint16_t sA[2][128 * PLD];
    __shared__ __align__(16) uint16_t sB[2][128 * PLD];

    const int tid  = threadIdx.x;
    const int wid  = tid >> 5, lane = tid & 31;
    const int g    = lane >> 2, t4 = lane & 3;
    const int wm   = wid & 3, wn = wid >> 2;
    const int m0   = blockIdx.x * 128, n0 = blockIdx.y * 128;

    float acc[2][8][4];
    #pragma unroll
    for (int i = 0; i < 2; i++)
        #pragma unroll
        for (int j = 0; j < 8; j++)
            #pragma unroll
            for (int r = 0; r < 4; r++) acc[i][j][r] = 0.0f;

    for (int k0 = 0; k0 < 256; k0 += 32) {
        #pragma unroll
        for (int i = 0; i < 4; i++) {
            int idx = tid + 256 * i;
            int r = idx >> 3, c4 = (idx & 7) << 2;
            float4 v = *(const float4*)(g_scratch + (size_t)(m0 + r) * 256 + k0 + c4);
            uint32_t h0 = pack_bf2(v.x, v.y), h1 = pack_bf2(v.z, v.w);
            float rx = v.x - bflo(h0), ry = v.y - bfhi(h0);
            float rz = v.z - bflo(h1), rw = v.w - bfhi(h1);
            *(uint2*)&sA[0][r * PLD + c4] = make_uint2(h0, h1);
            *(uint2*)&sA[1][r * PLD + c4] = make_uint2(pack_bf2(rx, ry), pack_bf2(rz, rw));
        }
        #pragma unroll
        for (int i = 0; i < 4; i++) {
            int idx = tid + 256 * i;
            int n = idx & 127, kg = idx >> 7;
            float w0 = Wt[(size_t)(k0 + kg * 4 + 0) * 256 + n0 + n];
            float w1 = Wt[(size_t)(k0 + kg * 4 + 1) * 256 + n0 + n];
            float w2 = Wt[(size_t)(k0 + kg * 4 + 2) * 256 + n0 + n];
            float w3 = Wt[(size_t)(k0 + kg * 4 + 3) * 256 + n0 + n];
            uint32_t h0 = pack_bf2(w0, w1), h1 = pack_bf2(w2, w3);
            float r0 = w0 - bflo(h0), r1 = w1 - bfhi(h0);
            float r2 = w2 - bflo(h1), r3 = w3 - bfhi(h1);
            *(uint2*)&sB[0][n * PLD + kg * 4] = make_uint2(h0, h1);
            *(uint2*)&sB[1][n * PLD + kg * 4] = make_uint2(pack_bf2(r0, r1), pack_bf2(r2, r3));
        }
        __syncthreads();

        #pragma unroll
        for (int ks = 0; ks < 32; ks += 16) {
            uint32_t ah[2][4], al[2][4], bh[8][2], bl[8][2];
            #pragma unroll
            for (int tm = 0; tm < 2; tm++) {
                int row = wm * 32 + tm * 16 + g;
                int kc  = ks + t4 * 2;
                ah[tm][0] = *(const uint32_t*)&sA[0][row * PLD + kc];
                ah[tm][1] = *(const uint32_t*)&sA[0][(row + 8) * PLD + kc];
                ah[tm][2] = *(const uint32_t*)&sA[0][row * PLD + kc + 8];
                ah[tm][3] = *(const uint32_t*)&sA[0][(row + 8) * PLD + kc + 8];
                al[tm][0] = *(const uint32_t*)&sA[1][row * PLD + kc];
                al[tm][1] = *(const uint32_t*)&sA[1][(row + 8) * PLD + kc];
                al[tm][2] = *(const uint32_t*)&sA[1][row * PLD + kc + 8];
                al[tm][3] = *(const uint32_t*)&sA[1][(row + 8) * PLD + kc + 8];
            }
            #pragma unroll
            for (int tn = 0; tn < 8; tn++) {
                int n  = wn * 64 + tn * 8 + g;
                int kc = ks + t4 * 2;
                bh[tn][0] = *(const uint32_t*)&sB[0][n * PLD + kc];
                bh[tn][1] = *(const uint32_t*)&sB[0][n * PLD + kc + 8];
                bl[tn][0] = *(const uint32_t*)&sB[1][n * PLD + kc];
                bl[tn][1] = *(const uint32_t*)&sB[1][n * PLD + kc + 8];
            }
            #pragma unroll
            for (int tm = 0; tm < 2; tm++)
                #pragma unroll
                for (int tn = 0; tn < 8; tn++) {
                    mma16816(acc[tm][tn], ah[tm], bh[tn]);
                    mma16816(acc[tm][tn], ah[tm], bl[tn]);
                    mma16816(acc[tm][tn], al[tm], bh[tn]);
                }
        }
        __syncthreads();
    }

    #pragma unroll
    for (int tm = 0; tm < 2; tm++) {
        int row = m0 + wm * 32 + tm * 16 + g;
        #pragma unroll
        for (int tn = 0; tn < 8; tn++) {
            int col = n0 + wn * 64 + tn * 8 + t4 * 2;
            float b0 = bias[col], b1 = bias[col + 1];
            *(float2*)(C + (size_t)row * 256 + col) =
                make_float2(acc[tm][tn][0] + b0, acc[tm][tn][1] + b1);
            *(float2*)(C + (size_t)(row + 8) * 256 + col) =
                make_float2(acc[tm][tn][2] + b0, acc[tm][tn][3] + b1);
        }
    }
}

// ---------------------------------------------------------------------------
extern "C" void kernel_launch(void* const* d_in, const int* in_sizes, int n_in,
                              void* d_out, int out_size)
{
    const float* x      = (const float*)d_in[0];
    const float* qkv_w  = (const float*)d_in[1];
    const float* qkv_b  = (const float*)d_in[2];
    const float* proj_w = (const float*)d_in[3];
    const float* proj_b = (const float*)d_in[4];
    const float* rpb    = (const float*)d_in[5];

    static int attr_set = 0;
    if (!attr_set) {
        cudaFuncSetAttribute(swin_attn_tc,
                             cudaFuncAttributeMaxDynamicSharedMemorySize, SMEM_TOT);
        attr_set = 1;
    }
    swin_attn_tc<<<BATCH * NWIN, 256, SMEM_TOT>>>(x, qkv_w, qkv_b, rpb);
    proj_mma_kernel<<<dim3(784, 2), 256>>>(proj_w, proj_b, (float*)d_out);
}